// round 12
// baseline (speedup 1.0000x reference)
#include <cuda_runtime.h>
#include <cuda_bf16.h>
#include <cfloat>
#include <climits>
#include <cstdint>

// ---------------- problem constants ----------------
#define NQ    2048
#define NK    65536
#define DIM   256
#define TOPK  32

// kernel-1 tiling
#define QT     128               // queries per CTA
#define NQT    (NQ / QT)         // 16
#define NSL    64                // key slices
#define SLKEYS (NK / NSL)        // 1024 keys per slice
#define TN     32                // keys per tile
#define NTILE  (SLKEYS / TN)     // 32
#define KPQ    12                // candidates kept per (query, slice)
#define KPQS   13
#define NCAND  (NSL * KPQ)       // 768 per query
#define NRES   48                // exact-rescored candidates

#define BROW   264               // Bs row stride in bf16 (528 B, conflict-free LDSM)
#define BSBYTES (TN * BROW * 2)  // one B buffer: 16896 B
#define SROW   34                // Ss row stride in floats

// ---------------- device scratch (globals, no allocs) ----------------
__device__ __nv_bfloat16 g_kb[(size_t)NK * DIM];   // 32 MB bf16 keys
__device__ float g_pv[(size_t)NQ * NCAND];         // 6 MB
__device__ int   g_pi[(size_t)NQ * NCAND];         // 6 MB

// ---------------- PTX helpers (base sm_103 ISA only) ----------------
__device__ __forceinline__ uint32_t smem_u32(const void* p) {
    uint32_t a;
    asm("{ .reg .u64 t; cvta.to.shared.u64 t, %1; cvt.u32.u64 %0, t; }" : "=r"(a) : "l"(p));
    return a;
}

// NON-trans: lane l gets stored-row l/4 (key), two consecutive stored cols (dims)
#define LDSM4(r, addr) \
    asm volatile("ldmatrix.sync.aligned.m8n8.x4.shared.b16 {%0,%1,%2,%3}, [%4];" \
        : "=r"((r)[0]), "=r"((r)[1]), "=r"((r)[2]), "=r"((r)[3]) : "r"(addr))

#define MMA16816(d, A, b0, b1) \
    asm volatile("mma.sync.aligned.m16n8k16.row.col.f32.bf16.bf16.f32 " \
        "{%0,%1,%2,%3}, {%4,%5,%6,%7}, {%8,%9}, {%0,%1,%2,%3};" \
        : "+f"((d)[0]), "+f"((d)[1]), "+f"((d)[2]), "+f"((d)[3]) \
        : "r"((A)[0]), "r"((A)[1]), "r"((A)[2]), "r"((A)[3]), "r"(b0), "r"(b1))

// ---------------- kernel 0: keys fp32 -> bf16 ----------------
__global__ __launch_bounds__(256)
void convert_keys_kernel(const float* __restrict__ keys) {
    size_t idx = ((size_t)blockIdx.x * 256 + threadIdx.x) * 8;
    float4 a = *(const float4*)(keys + idx);
    float4 b = *(const float4*)(keys + idx + 4);
    __nv_bfloat162 p0 = __float22bfloat162_rn(make_float2(a.x, a.y));
    __nv_bfloat162 p1 = __float22bfloat162_rn(make_float2(a.z, a.w));
    __nv_bfloat162 p2 = __float22bfloat162_rn(make_float2(b.x, b.y));
    __nv_bfloat162 p3 = __float22bfloat162_rn(make_float2(b.z, b.w));
    uint4 o;
    o.x = *(uint32_t*)&p0; o.y = *(uint32_t*)&p1;
    o.z = *(uint32_t*)&p2; o.w = *(uint32_t*)&p3;
    *(uint4*)(g_kb + idx) = o;
}

// ---------------- kernel 1: HMMA bf16 scores, reg-double-buffered B -------
// 128 threads (4 warps). Warp w owns queries [w*32, w*32+32).
// Next tile's LDGs are issued before the MMA loop (latency hidden), STS into
// the alternate buffer after; exactly ONE __syncthreads per tile.
__global__ __launch_bounds__(128, 2)
void score_topk_kernel(const float* __restrict__ query) {
    __shared__ __align__(16) __nv_bfloat16 Bs[2][TN * BROW];  // 33.8 KB
    __shared__ __align__(16) float Ss[QT * SROW];             // 17.4 KB
    __shared__ float Tv[QT * KPQS];                           // 6.7 KB
    __shared__ int   Ti[QT * KPQS];                           // 6.7 KB

    const int tid  = threadIdx.x;
    const int wid  = tid >> 5;
    const int lane = tid & 31;
    const int slice = blockIdx.x;
    const int qb    = blockIdx.y * QT;

    // ---- persistent A fragments (fp32 -> bf16 cvt in flight) ----
    uint32_t a[2][16][4];
    {
        const int tq = lane >> 2;
        const int tk = (lane & 3) * 2;
        #pragma unroll
        for (int mb = 0; mb < 2; ++mb) {
            const float* b0 = query + (size_t)(qb + wid * 32 + mb * 16 + tq) * DIM;
            const float* b1 = b0 + 8 * DIM;
            #pragma unroll
            for (int ks = 0; ks < 16; ++ks) {
                float2 f0 = *(const float2*)(b0 + ks * 16 + tk);
                float2 f1 = *(const float2*)(b1 + ks * 16 + tk);
                float2 f2 = *(const float2*)(b0 + ks * 16 + tk + 8);
                float2 f3 = *(const float2*)(b1 + ks * 16 + tk + 8);
                __nv_bfloat162 p0 = __float22bfloat162_rn(f0);
                __nv_bfloat162 p1 = __float22bfloat162_rn(f1);
                __nv_bfloat162 p2 = __float22bfloat162_rn(f2);
                __nv_bfloat162 p3 = __float22bfloat162_rn(f3);
                a[mb][ks][0] = *(uint32_t*)&p0;
                a[mb][ks][1] = *(uint32_t*)&p1;
                a[mb][ks][2] = *(uint32_t*)&p2;
                a[mb][ks][3] = *(uint32_t*)&p3;
            }
        }
    }

    // ---- top-k state (thread tid owns query tid) ----
    #pragma unroll
    for (int j = 0; j < KPQ; ++j) { Tv[tid * KPQS + j] = -FLT_MAX; Ti[tid * KPQS + j] = 0; }
    float minv = -FLT_MAX;
    int   minslot = 0;

    // ---- ldmatrix lane base offsets (non-trans x4, proven R6 layout) ----
    const uint32_t bs0 = smem_u32(&Bs[0][0]);
    const int keyA = ((lane >> 4) & 1) * 8 + (lane & 7);
    const uint32_t ldoff0 = (uint32_t)keyA * (BROW * 2) + (((lane >> 3) & 1) * 16);
    const uint32_t ldoff1 = ldoff0 + 16u * (BROW * 2);   // keys +16 (n-tiles 2,3)

    const int sq0 = wid * 32 + (lane >> 2);
    const int sk0 = (lane & 3) * 2;

    // ---- prologue: stage tile 0 into buf 0 ----
    {
        const __nv_bfloat16* kb = g_kb + ((size_t)slice * SLKEYS) * DIM;
        #pragma unroll
        for (int j = 0; j < 8; ++j) {
            int seg = tid + 128 * j;
            int key = seg >> 5, inr = seg & 31;
            uint4 v = *(const uint4*)(kb + key * DIM + inr * 8);
            *(uint4*)((char*)&Bs[0][0] + key * (BROW * 2) + inr * 16) = v;
        }
    }
    __syncthreads();

    float* Tr = Tv + tid * KPQS;
    int*   Ir = Ti + tid * KPQS;

    #pragma unroll 1
    for (int t = 0; t < NTILE; ++t) {
        // ---- issue next tile's LDGs into registers (latency hidden by MMA) ----
        uint4 p[8];
        const bool havenext = (t + 1 < NTILE);
        if (havenext) {
            const __nv_bfloat16* kb = g_kb + ((size_t)slice * SLKEYS + (size_t)(t + 1) * TN) * DIM;
            #pragma unroll
            for (int j = 0; j < 8; ++j) {
                int seg = tid + 128 * j;
                int key = seg >> 5, inr = seg & 31;
                p[j] = *(const uint4*)(kb + key * DIM + inr * 8);
            }
        }

        // ---- MMA over current buffer ----
        const uint32_t base = bs0 + (uint32_t)(t & 1) * BSBYTES;
        const uint32_t ld0 = base + ldoff0;
        const uint32_t ld1 = base + ldoff1;

        float c[2][4][4];
        #pragma unroll
        for (int mb = 0; mb < 2; ++mb)
            #pragma unroll
            for (int nt = 0; nt < 4; ++nt)
                #pragma unroll
                for (int e = 0; e < 4; ++e) c[mb][nt][e] = 0.0f;

        #pragma unroll
        for (int ks = 0; ks < 16; ++ks) {
            uint32_t b[8];
            LDSM4(b,     ld0 + ks * 32);   // keys 0-15:  nt0, nt1
            LDSM4(b + 4, ld1 + ks * 32);   // keys 16-31: nt2, nt3
            #pragma unroll
            for (int mb = 0; mb < 2; ++mb) {
                MMA16816(c[mb][0], a[mb][ks], b[0], b[1]);
                MMA16816(c[mb][1], a[mb][ks], b[2], b[3]);
                MMA16816(c[mb][2], a[mb][ks], b[4], b[5]);
                MMA16816(c[mb][3], a[mb][ks], b[6], b[7]);
            }
        }

        // ---- store staged next tile into the alternate buffer ----
        if (havenext) {
            char* dst = (char*)&Bs[(t + 1) & 1][0];
            #pragma unroll
            for (int j = 0; j < 8; ++j) {
                int seg = tid + 128 * j;
                int key = seg >> 5, inr = seg & 31;
                *(uint4*)(dst + key * (BROW * 2) + inr * 16) = p[j];
            }
        }

        // ---- D frags -> Ss (own warp's 32 queries) ----
        #pragma unroll
        for (int mb = 0; mb < 2; ++mb) {
            #pragma unroll
            for (int nt = 0; nt < 4; ++nt) {
                int q = sq0 + mb * 16;
                int k = nt * 8 + sk0;
                *(float2*)&Ss[q * SROW + k]       = make_float2(c[mb][nt][0], c[mb][nt][1]);
                *(float2*)&Ss[(q + 8) * SROW + k] = make_float2(c[mb][nt][2], c[mb][nt][3]);
            }
        }
        __syncwarp();

        // ---- streaming top-12: thread tid scans its query's 32 scores ----
        {
            const float* srow = Ss + tid * SROW;
            const int base2 = slice * SLKEYS + t * TN;
            #pragma unroll
            for (int k = 0; k < TN; ++k) {
                float s = srow[k];
                if (s > minv) {
                    Tr[minslot] = s; Ir[minslot] = base2 + k;
                    float m = Tr[0]; int ms = 0;
                    #pragma unroll
                    for (int j = 1; j < KPQ; ++j) {
                        float u = Tr[j];
                        if (u < m) { m = u; ms = j; }
                    }
                    minv = m; minslot = ms;
                }
            }
        }
        __syncthreads();   // STS(t+1) visible, Ss scans done, buf readers done
    }

    // ---- write per-slice candidates ----
    const size_t qg = (size_t)qb + tid;
    #pragma unroll
    for (int j = 0; j < KPQ; ++j) {
        g_pv[qg * NCAND + slice * KPQ + j] = Tr[j];
        g_pi[qg * NCAND + slice * KPQ + j] = Ir[j];
    }
}

// ---------------- kernel 2: merge + exact fp32 rescore + softmax + gather ---
__device__ __forceinline__ void amax3(float& v, int& i, int& p, float v2, int i2, int p2) {
    if (v2 > v || (v2 == v && i2 < i)) { v = v2; i = i2; p = p2; }
}

__global__ __launch_bounds__(256)
void merge_kernel(const float* __restrict__ query,
                  const float* __restrict__ keys,
                  const float* __restrict__ vals,
                  float* __restrict__ out) {
    __shared__ float cv[NCAND];
    __shared__ int   ci[NCAND];
    __shared__ float redv[8];
    __shared__ int   redi[8], redp[8];
    __shared__ int   candIdx[NRES];
    __shared__ float qrow[DIM];
    __shared__ float rs[NRES];
    __shared__ float selv[TOPK];
    __shared__ int   seli[TOPK];
    __shared__ float wts[TOPK];

    const int q = blockIdx.x;
    const int tid = threadIdx.x;
    const int w = tid >> 5, lane = tid & 31;

    for (int i = tid; i < NCAND; i += 256) {
        cv[i] = g_pv[(size_t)q * NCAND + i];
        ci[i] = g_pi[(size_t)q * NCAND + i];
    }
    qrow[tid] = query[(size_t)q * DIM + tid];
    __syncthreads();

    // --- approx top-48 (destructive argmax; tie-break lower key index) ---
    for (int it = 0; it < NRES; ++it) {
        float bv = -FLT_MAX; int bi = INT_MAX, bp = 0;
        #pragma unroll
        for (int r = 0; r < NCAND / 256; ++r) {
            int i = tid + r * 256;
            amax3(bv, bi, bp, cv[i], ci[i], i);
        }
        #pragma unroll
        for (int o = 16; o > 0; o >>= 1) {
            float ov = __shfl_xor_sync(0xffffffffu, bv, o);
            int oi = __shfl_xor_sync(0xffffffffu, bi, o);
            int op = __shfl_xor_sync(0xffffffffu, bp, o);
            amax3(bv, bi, bp, ov, oi, op);
        }
        if (lane == 0) { redv[w] = bv; redi[w] = bi; redp[w] = bp; }
        __syncthreads();
        if (tid == 0) {
            float fv = redv[0]; int fi = redi[0], fp = redp[0];
            #pragma unroll
            for (int k = 1; k < 8; ++k) amax3(fv, fi, fp, redv[k], redi[k], redp[k]);
            candIdx[it] = fi;
            cv[fp] = -FLT_MAX;
        }
        __syncthreads();
    }

    // --- exact fp32 rescore of the 48 candidates (6 per warp) ---
    #pragma unroll
    for (int r = 0; r < NRES / 8; ++r) {
        int j = w * (NRES / 8) + r;
        const float* kr = keys + (size_t)candIdx[j] * DIM;
        float acc = 0.0f;
        #pragma unroll
        for (int d = 0; d < DIM / 32; ++d)
            acc = fmaf(qrow[lane + d * 32], kr[lane + d * 32], acc);
        #pragma unroll
        for (int o = 16; o > 0; o >>= 1) acc += __shfl_xor_sync(0xffffffffu, acc, o);
        if (lane == 0) rs[j] = acc;
    }
    __syncthreads();

    // --- exact top-32 of the 48 rescored (warp 0; jax tie-break) ---
    if (w == 0) {
        for (int it = 0; it < TOPK; ++it) {
            float bv = rs[lane]; int bi = candIdx[lane], bp = lane;
            if (lane < NRES - 32) amax3(bv, bi, bp, rs[lane + 32], candIdx[lane + 32], lane + 32);
            #pragma unroll
            for (int o = 16; o > 0; o >>= 1) {
                float ov = __shfl_xor_sync(0xffffffffu, bv, o);
                int oi = __shfl_xor_sync(0xffffffffu, bi, o);
                int op = __shfl_xor_sync(0xffffffffu, bp, o);
                amax3(bv, bi, bp, ov, oi, op);
            }
            if (lane == 0) { selv[it] = bv; seli[it] = bi; rs[bp] = -FLT_MAX; }
            __syncwarp();
        }
        float s = selv[lane] * 0.0625f;   // D_MODEL^-0.5
        float m = s;
        #pragma unroll
        for (int o = 16; o > 0; o >>= 1) m = fmaxf(m, __shfl_xor_sync(0xffffffffu, m, o));
        float e = expf(s - m);
        float sum = e;
        #pragma unroll
        for (int o = 16; o > 0; o >>= 1) sum += __shfl_xor_sync(0xffffffffu, sum, o);
        wts[lane] = e / sum;
    }
    __syncthreads();

    // --- gather + weighted sum (thread = output dim) ---
    const int d = tid;
    float acc = 0.0f;
    #pragma unroll 8
    for (int j = 0; j < TOPK; ++j)
        acc += wts[j] * __ldg(vals + (size_t)seli[j] * DIM + d);
    out[(size_t)q * DIM + d] = acc;
}

// ---------------- host launch ----------------
extern "C" void kernel_launch(void* const* d_in, const int* in_sizes, int n_in,
                              void* d_out, int out_size) {
    const float* query = (const float*)d_in[0];   // [4,512,256]
    const float* keys  = (const float*)d_in[1];   // [65536,256]
    const float* vals  = (const float*)d_in[2];   // [65536,256]
    float* out = (float*)d_out;

    convert_keys_kernel<<<(NK * DIM) / (256 * 8), 256>>>(keys);
    score_topk_kernel<<<dim3(NSL, NQT), 128>>>(query);
    merge_kernel<<<NQ, 256>>>(query, keys, vals, out);
}

// round 13
// speedup vs baseline: 1.6370x; 1.6370x over previous
#include <cuda_runtime.h>
#include <cuda_bf16.h>
#include <cfloat>
#include <climits>
#include <cstdint>

// ---------------- problem constants ----------------
#define NQ    2048
#define NK    65536
#define DIM   256
#define TOPK  32

// kernel-1 tiling
#define QT     128               // queries per CTA
#define NQT    (NQ / QT)         // 16
#define NSL    64                // key slices
#define SLKEYS (NK / NSL)        // 1024 keys per slice
#define TN     32                // keys per tile
#define NTILE  (SLKEYS / TN)     // 32
#define KPQ    12                // candidates kept per (query, slice)
#define KPQS   13
#define NCAND  (NSL * KPQ)       // 768 per query
#define TARGET 40                // threshold rank for rescore set
#define CAP    160               // collected-candidate buffer

#define BROW   264               // Bs row stride in bf16 (528 B, conflict-free LDSM)
#define SROW   34                // Ss row stride in floats

// ---------------- device scratch (globals, no allocs) ----------------
__device__ __nv_bfloat16 g_kb[(size_t)NK * DIM];   // 32 MB bf16 keys
__device__ float g_pv[(size_t)NQ * NCAND];         // 6 MB
__device__ int   g_pi[(size_t)NQ * NCAND];         // 6 MB

// ---------------- PTX helpers (base sm_103 ISA only) ----------------
__device__ __forceinline__ uint32_t smem_u32(const void* p) {
    uint32_t a;
    asm("{ .reg .u64 t; cvta.to.shared.u64 t, %1; cvt.u32.u64 %0, t; }" : "=r"(a) : "l"(p));
    return a;
}

// NON-trans: lane l gets stored-row l/4 (key), two consecutive stored cols (dims)
#define LDSM4(r, addr) \
    asm volatile("ldmatrix.sync.aligned.m8n8.x4.shared.b16 {%0,%1,%2,%3}, [%4];" \
        : "=r"((r)[0]), "=r"((r)[1]), "=r"((r)[2]), "=r"((r)[3]) : "r"(addr))

#define MMA16816(d, A, b0, b1) \
    asm volatile("mma.sync.aligned.m16n8k16.row.col.f32.bf16.bf16.f32 " \
        "{%0,%1,%2,%3}, {%4,%5,%6,%7}, {%8,%9}, {%0,%1,%2,%3};" \
        : "+f"((d)[0]), "+f"((d)[1]), "+f"((d)[2]), "+f"((d)[3]) \
        : "r"((A)[0]), "r"((A)[1]), "r"((A)[2]), "r"((A)[3]), "r"(b0), "r"(b1))

// monotonic float -> uint mapping (order-preserving)
__device__ __forceinline__ uint32_t mono(float f) {
    uint32_t u = __float_as_uint(f);
    return (u & 0x80000000u) ? ~u : (u | 0x80000000u);
}

// ---------------- kernel 0: keys fp32 -> bf16 (proven R6) ----------------
__global__ __launch_bounds__(256)
void convert_keys_kernel(const float* __restrict__ keys) {
    size_t idx = ((size_t)blockIdx.x * 256 + threadIdx.x) * 8;
    float4 a = *(const float4*)(keys + idx);
    float4 b = *(const float4*)(keys + idx + 4);
    __nv_bfloat162 p0 = __float22bfloat162_rn(make_float2(a.x, a.y));
    __nv_bfloat162 p1 = __float22bfloat162_rn(make_float2(a.z, a.w));
    __nv_bfloat162 p2 = __float22bfloat162_rn(make_float2(b.x, b.y));
    __nv_bfloat162 p3 = __float22bfloat162_rn(make_float2(b.z, b.w));
    uint4 o;
    o.x = *(uint32_t*)&p0; o.y = *(uint32_t*)&p1;
    o.z = *(uint32_t*)&p2; o.w = *(uint32_t*)&p3;
    *(uint4*)(g_kb + idx) = o;
}

// ---------------- kernel 1: HMMA bf16 scores (byte-identical to R6) -------
__global__ __launch_bounds__(128, 2)
void score_topk_kernel(const float* __restrict__ query) {
    __shared__ __align__(16) __nv_bfloat16 Bs[TN * BROW];   // 16.9 KB
    __shared__ __align__(16) float Ss[QT * SROW];           // 17.4 KB
    __shared__ float Tv[QT * KPQS];                         // 6.7 KB
    __shared__ int   Ti[QT * KPQS];                         // 6.7 KB

    const int tid  = threadIdx.x;
    const int wid  = tid >> 5;
    const int lane = tid & 31;
    const int slice = blockIdx.x;
    const int qb    = blockIdx.y * QT;

    // ---- load persistent A fragments (fp32 -> bf16 cvt in flight) ----
    uint32_t a[2][16][4];
    {
        const int tq = lane >> 2;
        const int tk = (lane & 3) * 2;
        #pragma unroll
        for (int mb = 0; mb < 2; ++mb) {
            const float* b0 = query + (size_t)(qb + wid * 32 + mb * 16 + tq) * DIM;
            const float* b1 = b0 + 8 * DIM;
            #pragma unroll
            for (int ks = 0; ks < 16; ++ks) {
                float2 f0 = *(const float2*)(b0 + ks * 16 + tk);
                float2 f1 = *(const float2*)(b1 + ks * 16 + tk);
                float2 f2 = *(const float2*)(b0 + ks * 16 + tk + 8);
                float2 f3 = *(const float2*)(b1 + ks * 16 + tk + 8);
                __nv_bfloat162 p0 = __float22bfloat162_rn(f0);
                __nv_bfloat162 p1 = __float22bfloat162_rn(f1);
                __nv_bfloat162 p2 = __float22bfloat162_rn(f2);
                __nv_bfloat162 p3 = __float22bfloat162_rn(f3);
                a[mb][ks][0] = *(uint32_t*)&p0;
                a[mb][ks][1] = *(uint32_t*)&p1;
                a[mb][ks][2] = *(uint32_t*)&p2;
                a[mb][ks][3] = *(uint32_t*)&p3;
            }
        }
    }

    // ---- top-k state (thread tid owns query tid) ----
    #pragma unroll
    for (int j = 0; j < KPQ; ++j) { Tv[tid * KPQS + j] = -FLT_MAX; Ti[tid * KPQS + j] = 0; }
    float minv = -FLT_MAX;
    int   minslot = 0;

    // ---- ldmatrix lane base addresses (non-trans x4) ----
    const uint32_t bs_base = smem_u32(Bs);
    const int keyA = ((lane >> 4) & 1) * 8 + (lane & 7);
    const uint32_t ld0 = bs_base + (uint32_t)keyA * (BROW * 2) + (((lane >> 3) & 1) * 16);
    const uint32_t ld1 = ld0 + 16u * (BROW * 2);     // keys +16 (n-tiles 2,3)

    const int sq0 = wid * 32 + (lane >> 2);
    const int sk0 = (lane & 3) * 2;

    #pragma unroll 1
    for (int t = 0; t < NTILE; ++t) {
        // ---- stage 32 keys x 256 dims bf16 into Bs ----
        const __nv_bfloat16* kb = g_kb + ((size_t)slice * SLKEYS + (size_t)t * TN) * DIM;
        #pragma unroll
        for (int j = 0; j < 8; ++j) {
            int seg = tid + 128 * j;
            int key = seg >> 5, inr = seg & 31;
            uint4 v = *(const uint4*)(kb + key * DIM + inr * 8);
            *(uint4*)((char*)Bs + key * (BROW * 2) + inr * 16) = v;
        }
        __syncthreads();

        // ---- MMA: 2 m-blocks x 4 n-tiles x 16 k-steps ----
        float c[2][4][4];
        #pragma unroll
        for (int mb = 0; mb < 2; ++mb)
            #pragma unroll
            for (int nt = 0; nt < 4; ++nt)
                #pragma unroll
                for (int e = 0; e < 4; ++e) c[mb][nt][e] = 0.0f;

        #pragma unroll
        for (int ks = 0; ks < 16; ++ks) {
            uint32_t b[8];
            LDSM4(b,     ld0 + ks * 32);   // keys 0-15:  nt0, nt1
            LDSM4(b + 4, ld1 + ks * 32);   // keys 16-31: nt2, nt3
            #pragma unroll
            for (int mb = 0; mb < 2; ++mb) {
                MMA16816(c[mb][0], a[mb][ks], b[0], b[1]);
                MMA16816(c[mb][1], a[mb][ks], b[2], b[3]);
                MMA16816(c[mb][2], a[mb][ks], b[4], b[5]);
                MMA16816(c[mb][3], a[mb][ks], b[6], b[7]);
            }
        }

        // ---- D frags -> Ss (scores for this warp's 32 queries) ----
        #pragma unroll
        for (int mb = 0; mb < 2; ++mb) {
            #pragma unroll
            for (int nt = 0; nt < 4; ++nt) {
                int q = sq0 + mb * 16;
                int k = nt * 8 + sk0;
                *(float2*)&Ss[q * SROW + k]       = make_float2(c[mb][nt][0], c[mb][nt][1]);
                *(float2*)&Ss[(q + 8) * SROW + k] = make_float2(c[mb][nt][2], c[mb][nt][3]);
            }
        }
        __syncwarp();

        // ---- streaming top-12: thread tid scans its query's 32 scores ----
        {
            const float* srow = Ss + tid * SROW;
            const int base = slice * SLKEYS + t * TN;
            float* Tr = Tv + tid * KPQS;
            int*   Ir = Ti + tid * KPQS;
            #pragma unroll
            for (int k = 0; k < TN; ++k) {
                float s = srow[k];
                if (s > minv) {
                    Tr[minslot] = s; Ir[minslot] = base + k;
                    float m = Tr[0]; int ms = 0;
                    #pragma unroll
                    for (int j = 1; j < KPQ; ++j) {
                        float u = Tr[j];
                        if (u < m) { m = u; ms = j; }
                    }
                    minv = m; minslot = ms;
                }
            }
        }
        __syncthreads();
    }

    // ---- write per-slice candidates ----
    const size_t qg = (size_t)qb + tid;
    #pragma unroll
    for (int j = 0; j < KPQ; ++j) {
        g_pv[qg * NCAND + slice * KPQ + j] = Tv[tid * KPQS + j];
        g_pi[qg * NCAND + slice * KPQ + j] = Ti[tid * KPQS + j];
    }
}

// ---------------- kernel 2: histogram select + exact rescore (proven R7) --
__device__ __forceinline__ void amax3(float& v, int& i, int& p, float v2, int i2, int p2) {
    if (v2 > v || (v2 == v && i2 < i)) { v = v2; i = i2; p = p2; }
}

__global__ __launch_bounds__(256)
void merge_kernel(const float* __restrict__ query,
                  const float* __restrict__ keys,
                  const float* __restrict__ vals,
                  float* __restrict__ out) {
    __shared__ float cv[NCAND];
    __shared__ int   ci[NCAND];
    __shared__ int   hist[4096];
    __shared__ int   coarse[256];
    __shared__ int   thrBin, collN;
    __shared__ int   ridx[CAP];
    __shared__ float rs[CAP];
    __shared__ float qrow[DIM];
    __shared__ float selv[TOPK];
    __shared__ int   seli[TOPK];
    __shared__ float wts[TOPK];

    const int q = blockIdx.x;
    const int tid = threadIdx.x;
    const int w = tid >> 5, lane = tid & 31;

    for (int i = tid; i < NCAND; i += 256) {
        cv[i] = g_pv[(size_t)q * NCAND + i];
        ci[i] = g_pi[(size_t)q * NCAND + i];
    }
    qrow[tid] = query[(size_t)q * DIM + tid];
    #pragma unroll
    for (int j = 0; j < 16; ++j) hist[tid * 16 + j] = 0;
    if (tid == 0) collN = 0;
    __syncthreads();

    // --- histogram of monotonic-mapped bf16 scores (top 12 bits) ---
    for (int i = tid; i < NCAND; i += 256)
        atomicAdd(&hist[mono(cv[i]) >> 20], 1);
    __syncthreads();

    { int s = 0;
      #pragma unroll
      for (int j = 0; j < 16; ++j) s += hist[tid * 16 + j];
      coarse[tid] = s; }
    __syncthreads();

    // --- find threshold bin: smallest value bin s.t. count(>= bin) >= TARGET ---
    if (tid == 0) {
        int acc = 0, cb = 255;
        for (; cb >= 0; --cb) { acc += coarse[cb]; if (acc >= TARGET) break; }
        int acc2 = acc - coarse[cb];
        int fb = cb * 16 + 15;
        for (; fb > cb * 16; --fb) { acc2 += hist[fb]; if (acc2 >= TARGET) break; }
        if (acc2 < TARGET) fb = cb * 16;
        thrBin = fb;
    }
    __syncthreads();

    // --- collect all candidates at/above threshold bin ---
    const int tb = thrBin;
    for (int i = tid; i < NCAND; i += 256) {
        if ((int)(mono(cv[i]) >> 20) >= tb) {
            int p = atomicAdd(&collN, 1);
            if (p < CAP) ridx[p] = ci[i];
        }
    }
    __syncthreads();
    const int M = (collN < CAP) ? collN : CAP;
    for (int i = tid; i < CAP; i += 256)
        if (i >= M) { rs[i] = -FLT_MAX; ridx[i] = INT_MAX; }
    __syncthreads();

    // --- exact fp32 rescore of collected (one per warp, round-robin) ---
    for (int j = w; j < M; j += 8) {
        const float* kr = keys + (size_t)ridx[j] * DIM;
        float acc = 0.0f;
        #pragma unroll
        for (int d = 0; d < DIM / 32; ++d)
            acc = fmaf(qrow[lane + d * 32], kr[lane + d * 32], acc);
        #pragma unroll
        for (int o = 16; o > 0; o >>= 1) acc += __shfl_xor_sync(0xffffffffu, acc, o);
        if (lane == 0) rs[j] = acc;
    }
    __syncthreads();

    // --- exact top-32 over collected (warp 0; jax tie-break lower index) ---
    if (w == 0) {
        for (int it = 0; it < TOPK; ++it) {
            float bv = -FLT_MAX; int bi = INT_MAX, bp = 0;
            #pragma unroll
            for (int r = 0; r < CAP / 32; ++r) {
                int i = lane + r * 32;
                amax3(bv, bi, bp, rs[i], ridx[i], i);
            }
            #pragma unroll
            for (int o = 16; o > 0; o >>= 1) {
                float ov = __shfl_xor_sync(0xffffffffu, bv, o);
                int oi = __shfl_xor_sync(0xffffffffu, bi, o);
                int op = __shfl_xor_sync(0xffffffffu, bp, o);
                amax3(bv, bi, bp, ov, oi, op);
            }
            if (lane == 0) { selv[it] = bv; seli[it] = bi; rs[bp] = -FLT_MAX; }
            __syncwarp();
        }
        float s = selv[lane] * 0.0625f;   // D_MODEL^-0.5
        float m = s;
        #pragma unroll
        for (int o = 16; o > 0; o >>= 1) m = fmaxf(m, __shfl_xor_sync(0xffffffffu, m, o));
        float e = expf(s - m);
        float sum = e;
        #pragma unroll
        for (int o = 16; o > 0; o >>= 1) sum += __shfl_xor_sync(0xffffffffu, sum, o);
        wts[lane] = e / sum;
    }
    __syncthreads();

    // --- gather + weighted sum (thread = output dim) ---
    const int d = tid;
    float acc = 0.0f;
    #pragma unroll 8
    for (int j = 0; j < TOPK; ++j)
        acc += wts[j] * __ldg(vals + (size_t)seli[j] * DIM + d);
    out[(size_t)q * DIM + d] = acc;
}

// ---------------- host launch ----------------
extern "C" void kernel_launch(void* const* d_in, const int* in_sizes, int n_in,
                              void* d_out, int out_size) {
    const float* query = (const float*)d_in[0];   // [4,512,256]
    const float* keys  = (const float*)d_in[1];   // [65536,256]
    const float* vals  = (const float*)d_in[2];   // [65536,256]
    float* out = (float*)d_out;

    convert_keys_kernel<<<(NK * DIM) / (256 * 8), 256>>>(keys);
    score_topk_kernel<<<dim3(NSL, NQT), 128>>>(query);
    merge_kernel<<<NQ, 256>>>(query, keys, vals, out);
}

// round 14
// speedup vs baseline: 1.7508x; 1.0695x over previous
#include <cuda_runtime.h>
#include <cuda_fp16.h>
#include <cfloat>
#include <climits>
#include <cstdint>

// ---------------- problem constants ----------------
#define NQ    2048
#define NK    65536
#define DIM   256
#define TOPK  32

// kernel-1 tiling
#define QT     128               // queries per CTA
#define NQT    (NQ / QT)         // 16
#define NSL    64                // key slices
#define SLKEYS (NK / NSL)        // 1024 keys per slice
#define TN     32                // keys per tile
#define NTILE  (SLKEYS / TN)     // 32
#define KPQ    12                // candidates kept per (query, slice)
#define KPQS   13
#define NCAND  (NSL * KPQ)       // 768 per query
#define TARGET 40                // threshold rank for rescore set
#define CAP    160               // collected-candidate buffer

#define BROW   264               // Bs row stride in fp16 (528 B, conflict-free LDSM)
#define SROWU  17                // Ss row stride in uint32 (16 data + 1 pad)

// ---------------- device scratch (globals, no allocs) ----------------
__device__ __half g_kh[(size_t)NK * DIM];          // 32 MB fp16 keys
__device__ float g_pv[(size_t)NQ * NCAND];         // 6 MB
__device__ int   g_pi[(size_t)NQ * NCAND];         // 6 MB

// ---------------- PTX helpers (base sm_103 ISA only) ----------------
__device__ __forceinline__ uint32_t smem_u32(const void* p) {
    uint32_t a;
    asm("{ .reg .u64 t; cvta.to.shared.u64 t, %1; cvt.u32.u64 %0, t; }" : "=r"(a) : "l"(p));
    return a;
}

// NON-trans: lane l gets stored-row l/4 (key), two consecutive stored cols (dims)
#define LDSM4(r, addr) \
    asm volatile("ldmatrix.sync.aligned.m8n8.x4.shared.b16 {%0,%1,%2,%3}, [%4];" \
        : "=r"((r)[0]), "=r"((r)[1]), "=r"((r)[2]), "=r"((r)[3]) : "r"(addr))

// fp16 inputs, fp16 accumulate: D (2 regs) = A (4) x B (2) + D
#define MMA16816H(d, A, b0, b1) \
    asm volatile("mma.sync.aligned.m16n8k16.row.col.f16.f16.f16.f16 " \
        "{%0,%1}, {%2,%3,%4,%5}, {%6,%7}, {%0,%1};" \
        : "+r"((d)[0]), "+r"((d)[1]) \
        : "r"((A)[0]), "r"((A)[1]), "r"((A)[2]), "r"((A)[3]), "r"(b0), "r"(b1))

// monotonic float -> uint mapping (order-preserving)
__device__ __forceinline__ uint32_t mono(float f) {
    uint32_t u = __float_as_uint(f);
    return (u & 0x80000000u) ? ~u : (u | 0x80000000u);
}

// ---------------- kernel 0: keys fp32 -> fp16 ----------------
__global__ __launch_bounds__(256)
void convert_keys_kernel(const float* __restrict__ keys) {
    size_t idx = ((size_t)blockIdx.x * 256 + threadIdx.x) * 8;
    float4 a = *(const float4*)(keys + idx);
    float4 b = *(const float4*)(keys + idx + 4);
    __half2 p0 = __float22half2_rn(make_float2(a.x, a.y));
    __half2 p1 = __float22half2_rn(make_float2(a.z, a.w));
    __half2 p2 = __float22half2_rn(make_float2(b.x, b.y));
    __half2 p3 = __float22half2_rn(make_float2(b.z, b.w));
    uint4 o;
    o.x = *(uint32_t*)&p0; o.y = *(uint32_t*)&p1;
    o.z = *(uint32_t*)&p2; o.w = *(uint32_t*)&p3;
    *(uint4*)(g_kh + idx) = o;
}

// ---------------- kernel 1: fp16-acc HMMA scores + streaming top-12 -------
// 128 threads (4 warps). Warp w owns queries [w*32, w*32+32).
__global__ __launch_bounds__(128, 2)
void score_topk_kernel(const float* __restrict__ query) {
    __shared__ __align__(16) __half Bs[TN * BROW];          // 16.9 KB
    __shared__ __align__(16) uint32_t Ss[QT * SROWU];       // 8.7 KB
    __shared__ float Tv[QT * KPQS];                         // 6.7 KB
    __shared__ int   Ti[QT * KPQS];                         // 6.7 KB

    const int tid  = threadIdx.x;
    const int wid  = tid >> 5;
    const int lane = tid & 31;
    const int slice = blockIdx.x;
    const int qb    = blockIdx.y * QT;

    // ---- load persistent A fragments (fp32 -> fp16 cvt in flight) ----
    uint32_t a[2][16][4];
    {
        const int tq = lane >> 2;
        const int tk = (lane & 3) * 2;
        #pragma unroll
        for (int mb = 0; mb < 2; ++mb) {
            const float* b0 = query + (size_t)(qb + wid * 32 + mb * 16 + tq) * DIM;
            const float* b1 = b0 + 8 * DIM;
            #pragma unroll
            for (int ks = 0; ks < 16; ++ks) {
                float2 f0 = *(const float2*)(b0 + ks * 16 + tk);
                float2 f1 = *(const float2*)(b1 + ks * 16 + tk);
                float2 f2 = *(const float2*)(b0 + ks * 16 + tk + 8);
                float2 f3 = *(const float2*)(b1 + ks * 16 + tk + 8);
                __half2 p0 = __float22half2_rn(f0);
                __half2 p1 = __float22half2_rn(f1);
                __half2 p2 = __float22half2_rn(f2);
                __half2 p3 = __float22half2_rn(f3);
                a[mb][ks][0] = *(uint32_t*)&p0;
                a[mb][ks][1] = *(uint32_t*)&p1;
                a[mb][ks][2] = *(uint32_t*)&p2;
                a[mb][ks][3] = *(uint32_t*)&p3;
            }
        }
    }

    // ---- top-k state (thread tid owns query tid) ----
    #pragma unroll
    for (int j = 0; j < KPQ; ++j) { Tv[tid * KPQS + j] = -FLT_MAX; Ti[tid * KPQS + j] = 0; }
    float minv = -FLT_MAX;
    int   minslot = 0;

    // ---- ldmatrix lane base addresses (non-trans x4, proven layout) ----
    const uint32_t bs_base = smem_u32(Bs);
    const int keyA = ((lane >> 4) & 1) * 8 + (lane & 7);
    const uint32_t ld0 = bs_base + (uint32_t)keyA * (BROW * 2) + (((lane >> 3) & 1) * 16);
    const uint32_t ld1 = ld0 + 16u * (BROW * 2);     // keys +16 (n-tiles 2,3)

    const int sq0 = wid * 32 + (lane >> 2);
    const int sp  = lane & 3;                        // uint32 col within n-tile

    #pragma unroll 1
    for (int t = 0; t < NTILE; ++t) {
        // ---- stage 32 keys x 256 dims fp16 into Bs ----
        const __half* kb = g_kh + ((size_t)slice * SLKEYS + (size_t)t * TN) * DIM;
        #pragma unroll
        for (int j = 0; j < 8; ++j) {
            int seg = tid + 128 * j;
            int key = seg >> 5, inr = seg & 31;
            uint4 v = *(const uint4*)(kb + key * DIM + inr * 8);
            *(uint4*)((char*)Bs + key * (BROW * 2) + inr * 16) = v;
        }
        __syncthreads();

        // ---- MMA: 2 m-blocks x 4 n-tiles x 16 k-steps (fp16 acc) ----
        uint32_t c[2][4][2];
        #pragma unroll
        for (int mb = 0; mb < 2; ++mb)
            #pragma unroll
            for (int nt = 0; nt < 4; ++nt) { c[mb][nt][0] = 0u; c[mb][nt][1] = 0u; }

        #pragma unroll
        for (int ks = 0; ks < 16; ++ks) {
            uint32_t b[8];
            LDSM4(b,     ld0 + ks * 32);   // keys 0-15:  nt0, nt1
            LDSM4(b + 4, ld1 + ks * 32);   // keys 16-31: nt2, nt3
            #pragma unroll
            for (int mb = 0; mb < 2; ++mb) {
                MMA16816H(c[mb][0], a[mb][ks], b[0], b[1]);
                MMA16816H(c[mb][1], a[mb][ks], b[2], b[3]);
                MMA16816H(c[mb][2], a[mb][ks], b[4], b[5]);
                MMA16816H(c[mb][3], a[mb][ks], b[6], b[7]);
            }
        }

        // ---- D frags (half2) -> Ss: Ss32[q][nt*4+sp] halves = keys 2u,2u+1 ----
        #pragma unroll
        for (int mb = 0; mb < 2; ++mb) {
            #pragma unroll
            for (int nt = 0; nt < 4; ++nt) {
                int q = sq0 + mb * 16;
                Ss[q * SROWU + nt * 4 + sp]       = c[mb][nt][0];  // row g
                Ss[(q + 8) * SROWU + nt * 4 + sp] = c[mb][nt][1];  // row g+8
            }
        }
        __syncwarp();

        // ---- streaming top-12: thread tid scans its query's 32 scores ----
        {
            const uint32_t* srow = Ss + tid * SROWU;
            const int base = slice * SLKEYS + t * TN;
            float* Tr = Tv + tid * KPQS;
            int*   Ir = Ti + tid * KPQS;
            #pragma unroll
            for (int u = 0; u < 16; ++u) {
                uint32_t v = srow[u];
                float2 f = __half22float2(*(const __half2*)&v);
                if (f.x > minv) {
                    Tr[minslot] = f.x; Ir[minslot] = base + 2 * u;
                    float m = Tr[0]; int ms = 0;
                    #pragma unroll
                    for (int j = 1; j < KPQ; ++j) { float uu = Tr[j]; if (uu < m) { m = uu; ms = j; } }
                    minv = m; minslot = ms;
                }
                if (f.y > minv) {
                    Tr[minslot] = f.y; Ir[minslot] = base + 2 * u + 1;
                    float m = Tr[0]; int ms = 0;
                    #pragma unroll
                    for (int j = 1; j < KPQ; ++j) { float uu = Tr[j]; if (uu < m) { m = uu; ms = j; } }
                    minv = m; minslot = ms;
                }
            }
        }
        __syncthreads();
    }

    // ---- write per-slice candidates ----
    const size_t qg = (size_t)qb + tid;
    #pragma unroll
    for (int j = 0; j < KPQ; ++j) {
        g_pv[qg * NCAND + slice * KPQ + j] = Tv[tid * KPQS + j];
        g_pi[qg * NCAND + slice * KPQ + j] = Ti[tid * KPQS + j];
    }
}

// ---------------- kernel 2: histogram select + exact rescore (proven R13) --
__device__ __forceinline__ void amax3(float& v, int& i, int& p, float v2, int i2, int p2) {
    if (v2 > v || (v2 == v && i2 < i)) { v = v2; i = i2; p = p2; }
}

__global__ __launch_bounds__(256)
void merge_kernel(const float* __restrict__ query,
                  const float* __restrict__ keys,
                  const float* __restrict__ vals,
                  float* __restrict__ out) {
    __shared__ float cv[NCAND];
    __shared__ int   ci[NCAND];
    __shared__ int   hist[4096];
    __shared__ int   coarse[256];
    __shared__ int   thrBin, collN;
    __shared__ int   ridx[CAP];
    __shared__ float rs[CAP];
    __shared__ float qrow[DIM];
    __shared__ float selv[TOPK];
    __shared__ int   seli[TOPK];
    __shared__ float wts[TOPK];

    const int q = blockIdx.x;
    const int tid = threadIdx.x;
    const int w = tid >> 5, lane = tid & 31;

    for (int i = tid; i < NCAND; i += 256) {
        cv[i] = g_pv[(size_t)q * NCAND + i];
        ci[i] = g_pi[(size_t)q * NCAND + i];
    }
    qrow[tid] = query[(size_t)q * DIM + tid];
    #pragma unroll
    for (int j = 0; j < 16; ++j) hist[tid * 16 + j] = 0;
    if (tid == 0) collN = 0;
    __syncthreads();

    // --- histogram of monotonic-mapped scores (top 12 bits) ---
    for (int i = tid; i < NCAND; i += 256)
        atomicAdd(&hist[mono(cv[i]) >> 20], 1);
    __syncthreads();

    { int s = 0;
      #pragma unroll
      for (int j = 0; j < 16; ++j) s += hist[tid * 16 + j];
      coarse[tid] = s; }
    __syncthreads();

    // --- find threshold bin: smallest value bin s.t. count(>= bin) >= TARGET ---
    if (tid == 0) {
        int acc = 0, cb = 255;
        for (; cb >= 0; --cb) { acc += coarse[cb]; if (acc >= TARGET) break; }
        int acc2 = acc - coarse[cb];
        int fb = cb * 16 + 15;
        for (; fb > cb * 16; --fb) { acc2 += hist[fb]; if (acc2 >= TARGET) break; }
        if (acc2 < TARGET) fb = cb * 16;
        thrBin = fb;
    }
    __syncthreads();

    // --- collect all candidates at/above threshold bin ---
    const int tb = thrBin;
    for (int i = tid; i < NCAND; i += 256) {
        if ((int)(mono(cv[i]) >> 20) >= tb) {
            int p = atomicAdd(&collN, 1);
            if (p < CAP) ridx[p] = ci[i];
        }
    }
    __syncthreads();
    const int M = (collN < CAP) ? collN : CAP;
    for (int i = tid; i < CAP; i += 256)
        if (i >= M) { rs[i] = -FLT_MAX; ridx[i] = INT_MAX; }
    __syncthreads();

    // --- exact fp32 rescore of collected (one per warp, round-robin) ---
    for (int j = w; j < M; j += 8) {
        const float* kr = keys + (size_t)ridx[j] * DIM;
        float acc = 0.0f;
        #pragma unroll
        for (int d = 0; d < DIM / 32; ++d)
            acc = fmaf(qrow[lane + d * 32], kr[lane + d * 32], acc);
        #pragma unroll
        for (int o = 16; o > 0; o >>= 1) acc += __shfl_xor_sync(0xffffffffu, acc, o);
        if (lane == 0) rs[j] = acc;
    }
    __syncthreads();

    // --- exact top-32 over collected (warp 0; jax tie-break lower index) ---
    if (w == 0) {
        for (int it = 0; it < TOPK; ++it) {
            float bv = -FLT_MAX; int bi = INT_MAX, bp = 0;
            #pragma unroll
            for (int r = 0; r < CAP / 32; ++r) {
                int i = lane + r * 32;
                amax3(bv, bi, bp, rs[i], ridx[i], i);
            }
            #pragma unroll
            for (int o = 16; o > 0; o >>= 1) {
                float ov = __shfl_xor_sync(0xffffffffu, bv, o);
                int oi = __shfl_xor_sync(0xffffffffu, bi, o);
                int op = __shfl_xor_sync(0xffffffffu, bp, o);
                amax3(bv, bi, bp, ov, oi, op);
            }
            if (lane == 0) { selv[it] = bv; seli[it] = bi; rs[bp] = -FLT_MAX; }
            __syncwarp();
        }
        float s = selv[lane] * 0.0625f;   // D_MODEL^-0.5
        float m = s;
        #pragma unroll
        for (int o = 16; o > 0; o >>= 1) m = fmaxf(m, __shfl_xor_sync(0xffffffffu, m, o));
        float e = expf(s - m);
        float sum = e;
        #pragma unroll
        for (int o = 16; o > 0; o >>= 1) sum += __shfl_xor_sync(0xffffffffu, sum, o);
        wts[lane] = e / sum;
    }
    __syncthreads();

    // --- gather + weighted sum (thread = output dim) ---
    const int d = tid;
    float acc = 0.0f;
    #pragma unroll 8
    for (int j = 0; j < TOPK; ++j)
        acc += wts[j] * __ldg(vals + (size_t)seli[j] * DIM + d);
    out[(size_t)q * DIM + d] = acc;
}

// ---------------- host launch ----------------
extern "C" void kernel_launch(void* const* d_in, const int* in_sizes, int n_in,
                              void* d_out, int out_size) {
    const float* query = (const float*)d_in[0];   // [4,512,256]
    const float* keys  = (const float*)d_in[1];   // [65536,256]
    const float* vals  = (const float*)d_in[2];   // [65536,256]
    float* out = (float*)d_out;

    convert_keys_kernel<<<(NK * DIM) / (256 * 8), 256>>>(keys);
    score_topk_kernel<<<dim3(NSL, NQT), 128>>>(query);
    merge_kernel<<<NQ, 256>>>(query, keys, vals, out);
}